// round 16
// baseline (speedup 1.0000x reference)
#include <cuda_runtime.h>
#include <cuda_fp16.h>
#include <cstdint>
#include <math.h>

#define D_MODEL 1024
#define N_HEADS 16
#define D_HEAD  64
#define D_MLP   4096
#define BATCH   2
#define SEQ     2048
#define MROWS   (BATCH*SEQ)   /* 4096 */

// ---------------------------------------------------------------------------
// scratch (static device globals; no runtime alloc)
// ---------------------------------------------------------------------------
__device__ float   g_r2 [MROWS*D_MODEL];
__device__ __half  g_ln1[MROWS*D_MODEL];
__device__ __half  g_ln2[MROWS*D_MODEL];
__device__ __half  g_Qg[MROWS*D_MODEL];
__device__ __half  g_Kg[MROWS*D_MODEL];
__device__ __half  g_Vg[MROWS*D_MODEL];
__device__ __half  g_z [MROWS*D_MODEL];
__device__ __half  g_h [MROWS*D_MLP];
// transposed weights, [N][K] K-major, fp16
__device__ __half  g_Bqkv[3*D_MODEL*D_MODEL];
__device__ __half  g_Bo  [D_MODEL*D_MODEL];
__device__ __half  g_Bin [D_MLP*D_MODEL];
__device__ __half  g_Bout[D_MODEL*D_MLP];

// side stream + events for fork-join overlap (host-side objects only)
static cudaStream_t g_s1;
static cudaEvent_t  g_e0, g_e1, g_e2;
struct StreamInit {
    StreamInit() {
        cudaStreamCreateWithFlags(&g_s1, cudaStreamNonBlocking);
        cudaEventCreateWithFlags(&g_e0, cudaEventDisableTiming);
        cudaEventCreateWithFlags(&g_e1, cudaEventDisableTiming);
        cudaEventCreateWithFlags(&g_e2, cudaEventDisableTiming);
    }
};
static StreamInit g_stream_init;

// ---------------------------------------------------------------------------
// helpers
// ---------------------------------------------------------------------------
__device__ __forceinline__ uint32_t smem_to_u32(const void* p) {
    uint32_t a;
    asm("{ .reg .u64 t; cvta.to.shared.u64 t, %1; cvt.u32.u64 %0, t; }" : "=r"(a) : "l"(p));
    return a;
}
__device__ __forceinline__ void cp16(uint32_t s, const void* g) {
    asm volatile("cp.async.cg.shared.global [%0], [%1], 16;" :: "r"(s), "l"(g) : "memory");
}
#define CP_COMMIT()  asm volatile("cp.async.commit_group;" ::: "memory")
#define CP_WAIT2()   asm volatile("cp.async.wait_group 2;" ::: "memory")
#define CP_WAIT1()   asm volatile("cp.async.wait_group 1;" ::: "memory")
#define CP_WAIT0()   asm volatile("cp.async.wait_group 0;" ::: "memory")

__device__ __forceinline__ void ldm_x4(uint32_t* r, uint32_t a) {
    asm volatile("ldmatrix.sync.aligned.m8n8.x4.shared.b16 {%0,%1,%2,%3}, [%4];"
        : "=r"(r[0]), "=r"(r[1]), "=r"(r[2]), "=r"(r[3]) : "r"(a));
}
__device__ __forceinline__ void ldm_x4t(uint32_t* r, uint32_t a) {
    asm volatile("ldmatrix.sync.aligned.m8n8.x4.trans.shared.b16 {%0,%1,%2,%3}, [%4];"
        : "=r"(r[0]), "=r"(r[1]), "=r"(r[2]), "=r"(r[3]) : "r"(a));
}
__device__ __forceinline__ void mma_fp16(float* d, const uint32_t* a, const uint32_t* b) {
    asm volatile("mma.sync.aligned.m16n8k16.row.col.f32.f16.f16.f32 "
        "{%0,%1,%2,%3}, {%4,%5,%6,%7}, {%8,%9}, {%0,%1,%2,%3};"
        : "+f"(d[0]), "+f"(d[1]), "+f"(d[2]), "+f"(d[3])
        : "r"(a[0]), "r"(a[1]), "r"(a[2]), "r"(a[3]), "r"(b[0]), "r"(b[1]));
}

__device__ __forceinline__ uint32_t pack2f(float a, float b) {
    __half2 t = __floats2half2_rn(a, b);
    return *reinterpret_cast<uint32_t*>(&t);
}
// gelu via sigmoid identity
__device__ __forceinline__ float gelu_f(float x) {
    const float two_c = 1.5957691216057308f;
    float x2 = x * x;
    float u2 = two_c * (x + 0.044715f * x * x2);
    return x / (1.0f + __expf(-u2));
}

// ---------------------------------------------------------------------------
// layernorm -> fp16
// ---------------------------------------------------------------------------
__global__ __launch_bounds__(256)
void ln_h_kernel(const float* __restrict__ x, const float* __restrict__ w,
                 const float* __restrict__ b, __half* __restrict__ y)
{
    int row = blockIdx.x;
    int tid = threadIdx.x;
    const float4* xr = (const float4*)(x + (size_t)row * D_MODEL);
    float4 v = xr[tid];
    float s = v.x + v.y + v.z + v.w;

    __shared__ float red[8];
    #pragma unroll
    for (int o = 16; o > 0; o >>= 1) s += __shfl_xor_sync(0xffffffffu, s, o);
    if ((tid & 31) == 0) red[tid >> 5] = s;
    __syncthreads();
    float tot = 0.f;
    #pragma unroll
    for (int i = 0; i < 8; i++) tot += red[i];
    float mean = tot * (1.0f / D_MODEL);

    float dx = v.x - mean, dy = v.y - mean, dz = v.z - mean, dw = v.w - mean;
    float ss = dx*dx + dy*dy + dz*dz + dw*dw;
    __syncthreads();
    #pragma unroll
    for (int o = 16; o > 0; o >>= 1) ss += __shfl_xor_sync(0xffffffffu, ss, o);
    if ((tid & 31) == 0) red[tid >> 5] = ss;
    __syncthreads();
    float tvar = 0.f;
    #pragma unroll
    for (int i = 0; i < 8; i++) tvar += red[i];
    float inv = rsqrtf(tvar * (1.0f / D_MODEL) + 1e-5f);

    float4 wv = ((const float4*)w)[tid];
    float4 bv = ((const float4*)b)[tid];
    uint2 u;
    u.x = pack2f(dx * inv * wv.x + bv.x, dy * inv * wv.y + bv.y);
    u.y = pack2f(dz * inv * wv.z + bv.z, dw * inv * wv.w + bv.w);
    ((uint2*)(y + (size_t)row * D_MODEL))[tid] = u;
}

// ---------------------------------------------------------------------------
// weight transpose: in [R][C] fp32 -> out [C][R] fp16
// ---------------------------------------------------------------------------
__global__ __launch_bounds__(256)
void transpose_h(const float* __restrict__ in, __half* __restrict__ oh,
                 int R, int C, long inBatch, long outBatch)
{
    __shared__ float s[32][33];
    int tx = threadIdx.x & 31, ty = threadIdx.x >> 5;
    int c0 = blockIdx.x * 32, r0 = blockIdx.y * 32;
    long ib = (long)blockIdx.z * inBatch;
    long ob = (long)blockIdx.z * outBatch;
    #pragma unroll
    for (int i = 0; i < 4; i++)
        s[ty + 8*i][tx] = in[ib + (size_t)(r0 + ty + 8*i) * C + c0 + tx];
    __syncthreads();
    #pragma unroll
    for (int i = 0; i < 4; i++) {
        float x = s[tx][ty + 8*i];
        oh[ob + (size_t)(c0 + ty + 8*i) * R + r0 + tx] = __float2half_rn(x);
    }
}

// ---------------------------------------------------------------------------
// fp16 GEMM: C[M,N] = A[M,K] @ B[N,K]^T
// CTA 128x128x32, 8 warps (64x32 each); R14 loader/compute byte-identical;
// 3-stage cp.async ring (prefetch distance 2), R6 double-sync ordering.
// ---------------------------------------------------------------------------
#define ROWPAD  40
#define ROWB    (ROWPAD*2)               /* 80 B */
#define ARR_B   (128*ROWB)               /* 10240 B */
#define STG_B   (2*ARR_B)                /* 20480 B */
#define GEMM_SMEM (3*STG_B)              /* 61440 B */

#define EPI_QKV         0
#define EPI_RESID       1
#define EPI_GELU        2
#define EPI_BIAS_RESID  3

template<int EPI>
__global__ __launch_bounds__(256, 2)
void gemm_mma(const __half* __restrict__ Ah,
              const __half* __restrict__ Bh,
              float* __restrict__ C,
              __half* __restrict__ Ch,
              __half* __restrict__ Pk, __half* __restrict__ Pv,
              int K, int ldc,
              const float* __restrict__ bias, const float* __restrict__ resid)
{
    extern __shared__ char smem[];
    const uint32_t sb = smem_to_u32(smem);
    const int tid  = threadIdx.x;
    const int w    = tid >> 5;
    const int lane = tid & 31;
    const int m0 = blockIdx.y * 128;
    const int n0 = blockIdx.x * 128;

    const int wm0 = (w & 1) * 64;
    const int wn0 = (w >> 1) * 32;

    float acc[4][4][4];
    #pragma unroll
    for (int i = 0; i < 4; i++)
        #pragma unroll
        for (int j = 0; j < 4; j++)
            #pragma unroll
            for (int r = 0; r < 4; r++) acc[i][j][r] = 0.f;

    const int lrow0 = tid >> 2,  lkc0 = tid & 3;
    const int lrow1 = (tid + 256) >> 2, lkc1 = (tid + 256) & 3;

    auto load_stage = [&](int slot, int k0) {
        uint32_t st = sb + slot * STG_B;
        size_t ga0 = (size_t)(m0 + lrow0) * K + k0 + lkc0 * 8;
        size_t ga1 = (size_t)(m0 + lrow1) * K + k0 + lkc1 * 8;
        uint32_t sa0 = st + lrow0 * ROWB + lkc0 * 16;
        uint32_t sa1 = st + lrow1 * ROWB + lkc1 * 16;
        cp16(sa0, Ah + ga0);
        cp16(sa1, Ah + ga1);
        size_t gb0 = (size_t)(n0 + lrow0) * K + k0 + lkc0 * 8;
        size_t gb1 = (size_t)(n0 + lrow1) * K + k0 + lkc1 * 8;
        cp16(sa0 + ARR_B, Bh + gb0);
        cp16(sa1 + ARR_B, Bh + gb1);
    };

    const uint32_t aOff = (uint32_t)((wm0 + (lane & 15)) * ROWB + (lane >> 4) * 16);
    const uint32_t bOff = (uint32_t)((wn0 + (lane & 7) + ((lane >> 4) & 1) * 8) * ROWB
                                     + ((lane >> 3) & 1) * 16);

    const int NC = K / 32;
    load_stage(0, 0);
    CP_COMMIT();
    load_stage(1, 32);
    CP_COMMIT();

    for (int c = 0; c < NC; c++) {
        // prefetch stage c+2 into the slot freed by iteration c-1
        if (c + 2 < NC) { load_stage((c + 2) % 3, (c + 2) * 32); CP_COMMIT(); }
        // wait until stage c is resident (pending newer groups: c+1, c+2)
        if      (c + 2 < NC) { CP_WAIT2(); }
        else if (c + 1 < NC) { CP_WAIT1(); }
        else                 { CP_WAIT0(); }
        __syncthreads();

        uint32_t st = sb + (c % 3) * STG_B;
        uint32_t aBa = st + aOff;
        uint32_t bBa = st + ARR_B + bOff;

        #pragma unroll
        for (int ks = 0; ks < 2; ks++) {
            uint32_t ah[4][4], bh[4][2];
            #pragma unroll
            for (int mt = 0; mt < 4; mt++)
                ldm_x4(ah[mt], aBa + mt * 16 * ROWB + ks * 32);
            #pragma unroll
            for (int np = 0; np < 2; np++) {
                uint32_t rr[4];
                ldm_x4(rr, bBa + np * 16 * ROWB + ks * 32);
                bh[2*np][0]   = rr[0]; bh[2*np][1]   = rr[1];
                bh[2*np+1][0] = rr[2]; bh[2*np+1][1] = rr[3];
            }
            #pragma unroll
            for (int mt = 0; mt < 4; mt++)
                #pragma unroll
                for (int nt = 0; nt < 4; nt++)
                    mma_fp16(acc[mt][nt], ah[mt], bh[nt]);
        }
        __syncthreads();
    }

    // ---------------- epilogue ----------------
    #pragma unroll
    for (int mt = 0; mt < 4; mt++) {
        int r0 = m0 + wm0 + mt * 16 + (lane >> 2);
        #pragma unroll
        for (int nt = 0; nt < 4; nt++) {
            int cb = n0 + wn0 + nt * 8 + (lane & 3) * 2;
            float v00 = acc[mt][nt][0], v01 = acc[mt][nt][1];
            float v10 = acc[mt][nt][2], v11 = acc[mt][nt][3];
            if (EPI == EPI_QKV) {
                __half* dst;
                int cc = cb;
                if (cb < 1024)      { dst = Ch; }
                else if (cb < 2048) { dst = Pk; cc = cb - 1024; }
                else                { dst = Pv; cc = cb - 2048; }
                *(uint32_t*)(dst + (size_t)r0 * 1024 + cc)     = pack2f(v00, v01);
                *(uint32_t*)(dst + (size_t)(r0+8) * 1024 + cc) = pack2f(v10, v11);
            } else if (EPI == EPI_GELU) {
                v00 = gelu_f(v00 + bias[cb]);   v01 = gelu_f(v01 + bias[cb+1]);
                v10 = gelu_f(v10 + bias[cb]);   v11 = gelu_f(v11 + bias[cb+1]);
                *(uint32_t*)(Ch + (size_t)r0 * ldc + cb)     = pack2f(v00, v01);
                *(uint32_t*)(Ch + (size_t)(r0+8) * ldc + cb) = pack2f(v10, v11);
            } else {
                if (EPI == EPI_BIAS_RESID) {
                    v00 += bias[cb]; v01 += bias[cb+1];
                    v10 += bias[cb]; v11 += bias[cb+1];
                }
                float2 ra = *(const float2*)(resid + (size_t)r0 * ldc + cb);
                float2 rb = *(const float2*)(resid + (size_t)(r0+8) * ldc + cb);
                v00 += ra.x; v01 += ra.y; v10 += rb.x; v11 += rb.y;
                *(float2*)(C + (size_t)r0 * ldc + cb)     = make_float2(v00, v01);
                *(float2*)(C + (size_t)(r0+8) * ldc + cb) = make_float2(v10, v11);
            }
        }
    }
}

// ---------------------------------------------------------------------------
// tensor-core causal flash attention (fp16) — byte-exact R6/R14/R15 (proven).
// ---------------------------------------------------------------------------
#define KSTRIDE 72   /* halfs per smem row (144 B) */

__global__ __launch_bounds__(128)
void attn_tc(const __half* __restrict__ Qg,
             const __half* __restrict__ Kg, const __half* __restrict__ Vg,
             __half* __restrict__ Z)
{
    __shared__ __half Ks[2][64*KSTRIDE];
    __shared__ __half Vs[2][64*KSTRIDE];

    const int qt = (gridDim.x - 1) - blockIdx.x;   // big tiles first
    const int h  = blockIdx.y, b = blockIdx.z;
    const int tid = threadIdx.x;
    const int w = tid >> 5, lane = tid & 31;
    const int r = lane >> 2, c2 = (lane & 3) * 2;

    const uint32_t ksb = smem_to_u32(&Ks[0][0]);
    const uint32_t vsb = smem_to_u32(&Vs[0][0]);

    uint32_t qh[4][4];
    {
        size_t q0 = ((size_t)(b * SEQ + qt * 64 + w * 16 + r)) * 1024 + h * 64;
        size_t q8 = q0 + 8 * 1024;
        #pragma unroll
        for (int j = 0; j < 4; j++) {
            int kc = j * 16 + c2;
            qh[j][0] = *(const uint32_t*)(Qg + q0 + kc);
            qh[j][1] = *(const uint32_t*)(Qg + q8 + kc);
            qh[j][2] = *(const uint32_t*)(Qg + q0 + kc + 8);
            qh[j][3] = *(const uint32_t*)(Qg + q8 + kc + 8);
        }
    }

    auto load_kv = [&](int kt, int st) {
        size_t base = ((size_t)(b * SEQ + kt * 64)) * 1024 + h * 64;
        uint32_t kdst = ksb + st * (64*KSTRIDE*2);
        uint32_t vdst = vsb + st * (64*KSTRIDE*2);
        #pragma unroll
        for (int i = 0; i < 4; i++) {
            int ci = tid + 128 * i;
            int row = ci >> 3, c = ci & 7;
            cp16(kdst + row * (KSTRIDE*2) + c * 16, Kg + base + (size_t)row * 1024 + c * 8);
            cp16(vdst + row * (KSTRIDE*2) + c * 16, Vg + base + (size_t)row * 1024 + c * 8);
        }
    };

    float O[8][4];
    #pragma unroll
    for (int nt = 0; nt < 8; nt++)
        #pragma unroll
        for (int i = 0; i < 4; i++) O[nt][i] = 0.f;
    float m0 = -INFINITY, m1 = -INFINITY, l0 = 0.f, l1 = 0.f;

    const uint32_t kOff = (uint32_t)(((lane & 7) + ((lane >> 4) & 1) * 8) * (KSTRIDE*2)
                                     + ((lane >> 3) & 1) * 16);
    const uint32_t vOff = (uint32_t)(((lane & 7) + ((lane >> 3) & 1) * 8) * (KSTRIDE*2)
                                     + ((lane >> 4) & 1) * 16);

    load_kv(0, 0);
    CP_COMMIT();

    const int qrow_local = w * 16 + r;

    for (int kt = 0; kt <= qt; kt++) {
        if (kt < qt) { load_kv(kt + 1, (kt + 1) & 1); CP_COMMIT(); CP_WAIT1(); }
        else         { CP_WAIT0(); }
        __syncthreads();

        uint32_t kb_ = ksb + (kt & 1) * (64*KSTRIDE*2) + kOff;
        uint32_t vb_ = vsb + (kt & 1) * (64*KSTRIDE*2) + vOff;

        float S[8][4];
        #pragma unroll
        for (int nt = 0; nt < 8; nt++)
            #pragma unroll
            for (int i = 0; i < 4; i++) S[nt][i] = 0.f;

        #pragma unroll
        for (int j = 0; j < 4; j++) {
            uint32_t kf[8][2];
            #pragma unroll
            for (int np = 0; np < 4; np++) {
                uint32_t rr[4];
                ldm_x4(rr, kb_ + np * 16 * (KSTRIDE*2) + j * 32);
                kf[2*np][0] = rr[0]; kf[2*np][1] = rr[1];
                kf[2*np+1][0] = rr[2]; kf[2*np+1][1] = rr[3];
            }
            #pragma unroll
            for (int nt = 0; nt < 8; nt++)
                mma_fp16(S[nt], qh[j], kf[nt]);
        }

        bool diag = (kt == qt);
        #pragma unroll
        for (int nt = 0; nt < 8; nt++) {
            #pragma unroll
            for (int i = 0; i < 4; i++) {
                float s = S[nt][i] * 0.125f;
                if (diag) {
                    int col = nt * 8 + c2 + (i & 1);
                    int row = qrow_local + ((i >> 1) << 3);
                    if (col > row) s = -INFINITY;
                }
                S[nt][i] = s;
            }
        }

        float t0 = -INFINITY, t1 = -INFINITY;
        #pragma unroll
        for (int nt = 0; nt < 8; nt++) {
            t0 = fmaxf(t0, fmaxf(S[nt][0], S[nt][1]));
            t1 = fmaxf(t1, fmaxf(S[nt][2], S[nt][3]));
        }
        t0 = fmaxf(t0, __shfl_xor_sync(0xffffffffu, t0, 1));
        t0 = fmaxf(t0, __shfl_xor_sync(0xffffffffu, t0, 2));
        t1 = fmaxf(t1, __shfl_xor_sync(0xffffffffu, t1, 1));
        t1 = fmaxf(t1, __shfl_xor_sync(0xffffffffu, t1, 2));

        float mn0 = fmaxf(m0, t0), mn1 = fmaxf(m1, t1);
        float corr0 = __expf(m0 - mn0), corr1 = __expf(m1 - mn1);
        m0 = mn0; m1 = mn1;

        uint32_t P[8][2];
        float ps0 = 0.f, ps1 = 0.f;
        #pragma unroll
        for (int nt = 0; nt < 8; nt++) {
            float p00 = __expf(S[nt][0] - mn0);
            float p01 = __expf(S[nt][1] - mn0);
            float p10 = __expf(S[nt][2] - mn1);
            float p11 = __expf(S[nt][3] - mn1);
            ps0 += p00 + p01; ps1 += p10 + p11;
            P[nt][0] = pack2f(p00, p01);
            P[nt][1] = pack2f(p10, p11);
        }
        ps0 += __shfl_xor_sync(0xffffffffu, ps0, 1);
        ps0 += __shfl_xor_sync(0xffffffffu, ps0, 2);
        ps1 += __shfl_xor_sync(0xffffffffu, ps1, 1);
        ps1 += __shfl_xor_sync(0xffffffffu, ps1, 2);
        l0 = l0 * corr0 + ps0;
        l1 = l1 * corr1 + ps1;

        #pragma unroll
        for (int nt = 0; nt < 8; nt++) {
            O[nt][0] *= corr0; O[nt][1] *= corr0;
            O[nt][2] *= corr1; O[nt][3] *= corr1;
        }

        #pragma unroll
        for (int j = 0; j < 4; j++) {
            uint32_t pf[4] = { P[2*j][0], P[2*j][1], P[2*j+1][0], P[2*j+1][1] };
            uint32_t vf[8][2];
            #pragma unroll
            for (int np = 0; np < 4; np++) {
                uint32_t rr[4];
                ldm_x4t(rr, vb_ + j * 16 * (KSTRIDE*2) + np * 32);
                vf[2*np][0] = rr[0]; vf[2*np][1] = rr[1];
                vf[2*np+1][0] = rr[2]; vf[2*np+1][1] = rr[3];
            }
            #pragma unroll
            for (int nt = 0; nt < 8; nt++)
                mma_fp16(O[nt], pf, vf[nt]);
        }
        __syncthreads();
    }

    float inv0 = 1.0f / l0, inv1 = 1.0f / l1;
    size_t z0 = ((size_t)(b * SEQ + qt * 64 + qrow_local)) * 1024 + h * 64 + c2;
    size_t z8 = z0 + 8 * 1024;
    #pragma unroll
    for (int nt = 0; nt < 8; nt++) {
        *(uint32_t*)(Z + z0 + nt*8) = pack2f(O[nt][0] * inv0, O[nt][1] * inv0);
        *(uint32_t*)(Z + z8 + nt*8) = pack2f(O[nt][2] * inv1, O[nt][3] * inv1);
    }
}

// ---------------------------------------------------------------------------
// host orchestration (fork-join: transposes on side stream, proven R15)
// ---------------------------------------------------------------------------
extern "C" void kernel_launch(void* const* d_in, const int* in_sizes, int n_in,
                              void* d_out, int out_size)
{
    const float* resid = (const float*)d_in[0];
    const float* w_q   = (const float*)d_in[1];
    const float* w_k   = (const float*)d_in[2];
    const float* w_v   = (const float*)d_in[3];
    const float* w_o   = (const float*)d_in[4];
    const float* ln1_w = (const float*)d_in[5];
    const float* ln1_b = (const float*)d_in[6];
    const float* ln2_w = (const float*)d_in[7];
    const float* ln2_b = (const float*)d_in[8];
    const float* w_in  = (const float*)d_in[9];
    const float* b_in  = (const float*)d_in[10];
    const float* w_out = (const float*)d_in[11];
    const float* b_out = (const float*)d_in[12];
    float* out = (float*)d_out;

    float *r2;
    __half *ln1, *ln2, *qg, *kg, *vg, *z, *hb;
    __half *Bqkv, *Bo, *Bin, *Bout;
    cudaGetSymbolAddress((void**)&r2,   g_r2);
    cudaGetSymbolAddress((void**)&ln1,  g_ln1);
    cudaGetSymbolAddress((void**)&ln2,  g_ln2);
    cudaGetSymbolAddress((void**)&qg,   g_Qg);
    cudaGetSymbolAddress((void**)&kg,   g_Kg);
    cudaGetSymbolAddress((void**)&vg,   g_Vg);
    cudaGetSymbolAddress((void**)&z,    g_z);
    cudaGetSymbolAddress((void**)&hb,   g_h);
    cudaGetSymbolAddress((void**)&Bqkv, g_Bqkv);
    cudaGetSymbolAddress((void**)&Bo,   g_Bo);
    cudaGetSymbolAddress((void**)&Bin,  g_Bin);
    cudaGetSymbolAddress((void**)&Bout, g_Bout);

    cudaFuncSetAttribute(gemm_mma<EPI_QKV>,        cudaFuncAttributeMaxDynamicSharedMemorySize, GEMM_SMEM);
    cudaFuncSetAttribute(gemm_mma<EPI_RESID>,      cudaFuncAttributeMaxDynamicSharedMemorySize, GEMM_SMEM);
    cudaFuncSetAttribute(gemm_mma<EPI_GELU>,       cudaFuncAttributeMaxDynamicSharedMemorySize, GEMM_SMEM);
    cudaFuncSetAttribute(gemm_mma<EPI_BIAS_RESID>, cudaFuncAttributeMaxDynamicSharedMemorySize, GEMM_SMEM);

    // ---- fork: side stream does all weight transposes ----
    cudaEventRecord(g_e0, 0);
    cudaStreamWaitEvent(g_s1, g_e0, 0);

    transpose_h<<<dim3(2, 32, 16), 256, 0, g_s1>>>(w_q, Bqkv,             1024, 64, 65536, 65536);
    transpose_h<<<dim3(2, 32, 16), 256, 0, g_s1>>>(w_k, Bqkv + 1024*1024, 1024, 64, 65536, 65536);
    transpose_h<<<dim3(2, 32, 16), 256, 0, g_s1>>>(w_v, Bqkv + 2048*1024, 1024, 64, 65536, 65536);
    cudaEventRecord(g_e1, g_s1);          // Bqkv ready

    transpose_h<<<dim3(32, 32, 1),  256, 0, g_s1>>>(w_o,   Bo,   1024, 1024, 0, 0);
    transpose_h<<<dim3(128, 32, 1), 256, 0, g_s1>>>(w_in,  Bin,  1024, 4096, 0, 0);
    transpose_h<<<dim3(32, 128, 1), 256, 0, g_s1>>>(w_out, Bout, 4096, 1024, 0, 0);
    cudaEventRecord(g_e2, g_s1);          // Bo/Bin/Bout ready

    // ---- main stream: ln1 overlaps Bqkv transposes ----
    ln_h_kernel<<<MROWS, 256>>>(resid, ln1_w, ln1_b, ln1);

    cudaStreamWaitEvent(0, g_e1, 0);      // join: Bqkv needed now
    gemm_mma<EPI_QKV><<<dim3(24, 32), 256, GEMM_SMEM>>>(
        ln1, Bqkv, nullptr, qg, kg, vg, 1024, 3072, nullptr, nullptr);

    attn_tc<<<dim3(SEQ / 64, N_HEADS, BATCH), 128>>>(qg, kg, vg, z);

    cudaStreamWaitEvent(0, g_e2, 0);      // join: Bo/Bin/Bout needed from here
    gemm_mma<EPI_RESID><<<dim3(8, 32), 256, GEMM_SMEM>>>(
        z, Bo, r2, nullptr, nullptr, nullptr, 1024, 1024, nullptr, resid);

    ln_h_kernel<<<MROWS, 256>>>(r2, ln2_w, ln2_b, ln2);

    gemm_mma<EPI_GELU><<<dim3(32, 32), 256, GEMM_SMEM>>>(
        ln2, Bin, nullptr, hb, nullptr, nullptr, 1024, 4096, b_in, nullptr);

    gemm_mma<EPI_BIAS_RESID><<<dim3(8, 32), 256, GEMM_SMEM>>>(
        hb, Bout, out, nullptr, nullptr, nullptr, 4096, 1024, b_out, r2);
}

// round 17
// speedup vs baseline: 1.0557x; 1.0557x over previous
#include <cuda_runtime.h>
#include <cuda_fp16.h>
#include <cstdint>
#include <math.h>

#define D_MODEL 1024
#define N_HEADS 16
#define D_HEAD  64
#define D_MLP   4096
#define BATCH   2
#define SEQ     2048
#define MROWS   (BATCH*SEQ)   /* 4096 */

// ---------------------------------------------------------------------------
// scratch (static device globals; no runtime alloc)
// ---------------------------------------------------------------------------
__device__ float   g_r2 [MROWS*D_MODEL];
__device__ __half  g_ln1[MROWS*D_MODEL];
__device__ __half  g_ln2[MROWS*D_MODEL];
__device__ __half  g_Qg[MROWS*D_MODEL];
__device__ __half  g_Kg[MROWS*D_MODEL];
__device__ __half  g_Vg[MROWS*D_MODEL];
__device__ __half  g_z [MROWS*D_MODEL];
__device__ __half  g_h [MROWS*D_MLP];
// transposed weights, [N][K] K-major, fp16
__device__ __half  g_Bqkv[3*D_MODEL*D_MODEL];
__device__ __half  g_Bo  [D_MODEL*D_MODEL];
__device__ __half  g_Bin [D_MLP*D_MODEL];
__device__ __half  g_Bout[D_MODEL*D_MLP];

// side stream + events for fork-join overlap (host-side objects only)
static cudaStream_t g_s1;
static cudaEvent_t  g_e0, g_e1, g_e2;
struct StreamInit {
    StreamInit() {
        cudaStreamCreateWithFlags(&g_s1, cudaStreamNonBlocking);
        cudaEventCreateWithFlags(&g_e0, cudaEventDisableTiming);
        cudaEventCreateWithFlags(&g_e1, cudaEventDisableTiming);
        cudaEventCreateWithFlags(&g_e2, cudaEventDisableTiming);
    }
};
static StreamInit g_stream_init;

// ---------------------------------------------------------------------------
// helpers
// ---------------------------------------------------------------------------
__device__ __forceinline__ uint32_t smem_to_u32(const void* p) {
    uint32_t a;
    asm("{ .reg .u64 t; cvta.to.shared.u64 t, %1; cvt.u32.u64 %0, t; }" : "=r"(a) : "l"(p));
    return a;
}
__device__ __forceinline__ void cp16(uint32_t s, const void* g) {
    asm volatile("cp.async.cg.shared.global [%0], [%1], 16;" :: "r"(s), "l"(g) : "memory");
}
#define CP_COMMIT()  asm volatile("cp.async.commit_group;" ::: "memory")
#define CP_WAIT1()   asm volatile("cp.async.wait_group 1;" ::: "memory")
#define CP_WAIT0()   asm volatile("cp.async.wait_group 0;" ::: "memory")

__device__ __forceinline__ void ldm_x4(uint32_t* r, uint32_t a) {
    asm volatile("ldmatrix.sync.aligned.m8n8.x4.shared.b16 {%0,%1,%2,%3}, [%4];"
        : "=r"(r[0]), "=r"(r[1]), "=r"(r[2]), "=r"(r[3]) : "r"(a));
}
__device__ __forceinline__ void ldm_x4t(uint32_t* r, uint32_t a) {
    asm volatile("ldmatrix.sync.aligned.m8n8.x4.trans.shared.b16 {%0,%1,%2,%3}, [%4];"
        : "=r"(r[0]), "=r"(r[1]), "=r"(r[2]), "=r"(r[3]) : "r"(a));
}
__device__ __forceinline__ void mma_fp16(float* d, const uint32_t* a, const uint32_t* b) {
    asm volatile("mma.sync.aligned.m16n8k16.row.col.f32.f16.f16.f32 "
        "{%0,%1,%2,%3}, {%4,%5,%6,%7}, {%8,%9}, {%0,%1,%2,%3};"
        : "+f"(d[0]), "+f"(d[1]), "+f"(d[2]), "+f"(d[3])
        : "r"(a[0]), "r"(a[1]), "r"(a[2]), "r"(a[3]), "r"(b[0]), "r"(b[1]));
}

__device__ __forceinline__ uint32_t pack2f(float a, float b) {
    __half2 t = __floats2half2_rn(a, b);
    return *reinterpret_cast<uint32_t*>(&t);
}
// gelu via sigmoid identity
__device__ __forceinline__ float gelu_f(float x) {
    const float two_c = 1.5957691216057308f;
    float x2 = x * x;
    float u2 = two_c * (x + 0.044715f * x * x2);
    return x / (1.0f + __expf(-u2));
}

// ---------------------------------------------------------------------------
// layernorm -> fp16
// ---------------------------------------------------------------------------
__global__ __launch_bounds__(256)
void ln_h_kernel(const float* __restrict__ x, const float* __restrict__ w,
                 const float* __restrict__ b, __half* __restrict__ y)
{
    int row = blockIdx.x;
    int tid = threadIdx.x;
    const float4* xr = (const float4*)(x + (size_t)row * D_MODEL);
    float4 v = xr[tid];
    float s = v.x + v.y + v.z + v.w;

    __shared__ float red[8];
    #pragma unroll
    for (int o = 16; o > 0; o >>= 1) s += __shfl_xor_sync(0xffffffffu, s, o);
    if ((tid & 31) == 0) red[tid >> 5] = s;
    __syncthreads();
    float tot = 0.f;
    #pragma unroll
    for (int i = 0; i < 8; i++) tot += red[i];
    float mean = tot * (1.0f / D_MODEL);

    float dx = v.x - mean, dy = v.y - mean, dz = v.z - mean, dw = v.w - mean;
    float ss = dx*dx + dy*dy + dz*dz + dw*dw;
    __syncthreads();
    #pragma unroll
    for (int o = 16; o > 0; o >>= 1) ss += __shfl_xor_sync(0xffffffffu, ss, o);
    if ((tid & 31) == 0) red[tid >> 5] = ss;
    __syncthreads();
    float tvar = 0.f;
    #pragma unroll
    for (int i = 0; i < 8; i++) tvar += red[i];
    float inv = rsqrtf(tvar * (1.0f / D_MODEL) + 1e-5f);

    float4 wv = ((const float4*)w)[tid];
    float4 bv = ((const float4*)b)[tid];
    uint2 u;
    u.x = pack2f(dx * inv * wv.x + bv.x, dy * inv * wv.y + bv.y);
    u.y = pack2f(dz * inv * wv.z + bv.z, dw * inv * wv.w + bv.w);
    ((uint2*)(y + (size_t)row * D_MODEL))[tid] = u;
}

// ---------------------------------------------------------------------------
// weight transpose: in [R][C] fp32 -> out [C][R] fp16
// ---------------------------------------------------------------------------
__global__ __launch_bounds__(256)
void transpose_h(const float* __restrict__ in, __half* __restrict__ oh,
                 int R, int C, long inBatch, long outBatch)
{
    __shared__ float s[32][33];
    int tx = threadIdx.x & 31, ty = threadIdx.x >> 5;
    int c0 = blockIdx.x * 32, r0 = blockIdx.y * 32;
    long ib = (long)blockIdx.z * inBatch;
    long ob = (long)blockIdx.z * outBatch;
    #pragma unroll
    for (int i = 0; i < 4; i++)
        s[ty + 8*i][tx] = in[ib + (size_t)(r0 + ty + 8*i) * C + c0 + tx];
    __syncthreads();
    #pragma unroll
    for (int i = 0; i < 4; i++) {
        float x = s[tx][ty + 8*i];
        oh[ob + (size_t)(c0 + ty + 8*i) * R + r0 + tx] = __float2half_rn(x);
    }
}

// ---------------------------------------------------------------------------
// fp16 GEMM: C[M,N] = A[M,K] @ B[N,K]^T  — R15 semantics, mainloop unrolled x2
// (slot index compile-time; NC = K/32 is even for K in {1024, 4096}).
// CTA 128x128x32, 8 warps (64x32 each), cp.async double-buffer.
// ---------------------------------------------------------------------------
#define ROWPAD  40
#define ROWB    (ROWPAD*2)               /* 80 B */
#define ARR_B   (128*ROWB)               /* 10240 B */
#define STG_B   (2*ARR_B)                /* 20480 B */
#define GEMM_SMEM (2*STG_B)              /* 40960 B */

#define EPI_QKV         0
#define EPI_RESID       1
#define EPI_GELU        2
#define EPI_BIAS_RESID  3

template<int EPI>
__global__ __launch_bounds__(256, 2)
void gemm_mma(const __half* __restrict__ Ah,
              const __half* __restrict__ Bh,
              float* __restrict__ C,
              __half* __restrict__ Ch,
              __half* __restrict__ Pk, __half* __restrict__ Pv,
              int K, int ldc,
              const float* __restrict__ bias, const float* __restrict__ resid)
{
    extern __shared__ char smem[];
    const uint32_t sb = smem_to_u32(smem);
    const int tid  = threadIdx.x;
    const int w    = tid >> 5;
    const int lane = tid & 31;
    const int m0 = blockIdx.y * 128;
    const int n0 = blockIdx.x * 128;

    const int wm0 = (w & 1) * 64;
    const int wn0 = (w >> 1) * 32;

    float acc[4][4][4];
    #pragma unroll
    for (int i = 0; i < 4; i++)
        #pragma unroll
        for (int j = 0; j < 4; j++)
            #pragma unroll
            for (int r = 0; r < 4; r++) acc[i][j][r] = 0.f;

    const int lrow0 = tid >> 2,  lkc0 = tid & 3;
    const int lrow1 = (tid + 256) >> 2, lkc1 = (tid + 256) & 3;

    auto load_stage = [&](int slot, int k0) {
        uint32_t st = sb + slot * STG_B;
        size_t ga0 = (size_t)(m0 + lrow0) * K + k0 + lkc0 * 8;
        size_t ga1 = (size_t)(m0 + lrow1) * K + k0 + lkc1 * 8;
        uint32_t sa0 = st + lrow0 * ROWB + lkc0 * 16;
        uint32_t sa1 = st + lrow1 * ROWB + lkc1 * 16;
        cp16(sa0, Ah + ga0);
        cp16(sa1, Ah + ga1);
        size_t gb0 = (size_t)(n0 + lrow0) * K + k0 + lkc0 * 8;
        size_t gb1 = (size_t)(n0 + lrow1) * K + k0 + lkc1 * 8;
        cp16(sa0 + ARR_B, Bh + gb0);
        cp16(sa1 + ARR_B, Bh + gb1);
    };

    const uint32_t aOff = (uint32_t)((wm0 + (lane & 15)) * ROWB + (lane >> 4) * 16);
    const uint32_t bOff = (uint32_t)((wn0 + (lane & 7) + ((lane >> 4) & 1) * 8) * ROWB
                                     + ((lane >> 3) & 1) * 16);

    auto compute_slot = [&](uint32_t stBase) {
        uint32_t aBa = stBase + aOff;
        uint32_t bBa = stBase + ARR_B + bOff;
        #pragma unroll
        for (int ks = 0; ks < 2; ks++) {
            uint32_t ah[4][4], bh[4][2];
            #pragma unroll
            for (int mt = 0; mt < 4; mt++)
                ldm_x4(ah[mt], aBa + mt * 16 * ROWB + ks * 32);
            #pragma unroll
            for (int np = 0; np < 2; np++) {
                uint32_t rr[4];
                ldm_x4(rr, bBa + np * 16 * ROWB + ks * 32);
                bh[2*np][0]   = rr[0]; bh[2*np][1]   = rr[1];
                bh[2*np+1][0] = rr[2]; bh[2*np+1][1] = rr[3];
            }
            #pragma unroll
            for (int mt = 0; mt < 4; mt++)
                #pragma unroll
                for (int nt = 0; nt < 4; nt++)
                    mma_fp16(acc[mt][nt], ah[mt], bh[nt]);
        }
    };

    const int NC = K / 32;   // even (32 or 128)
    load_stage(0, 0);
    CP_COMMIT();

    for (int c = 0; c < NC; c += 2) {
        // ---- iteration c (slot 0) ----
        load_stage(1, (c + 1) * 32);   // c+1 < NC always (NC even)
        CP_COMMIT();
        CP_WAIT1();
        __syncthreads();
        compute_slot(sb);
        __syncthreads();

        // ---- iteration c+1 (slot 1) ----
        if (c + 2 < NC) { load_stage(0, (c + 2) * 32); CP_COMMIT(); CP_WAIT1(); }
        else            { CP_WAIT0(); }
        __syncthreads();
        compute_slot(sb + STG_B);
        __syncthreads();
    }

    // ---------------- epilogue ----------------
    #pragma unroll
    for (int mt = 0; mt < 4; mt++) {
        int r0 = m0 + wm0 + mt * 16 + (lane >> 2);
        #pragma unroll
        for (int nt = 0; nt < 4; nt++) {
            int cb = n0 + wn0 + nt * 8 + (lane & 3) * 2;
            float v00 = acc[mt][nt][0], v01 = acc[mt][nt][1];
            float v10 = acc[mt][nt][2], v11 = acc[mt][nt][3];
            if (EPI == EPI_QKV) {
                __half* dst;
                int cc = cb;
                if (cb < 1024)      { dst = Ch; }
                else if (cb < 2048) { dst = Pk; cc = cb - 1024; }
                else                { dst = Pv; cc = cb - 2048; }
                *(uint32_t*)(dst + (size_t)r0 * 1024 + cc)     = pack2f(v00, v01);
                *(uint32_t*)(dst + (size_t)(r0+8) * 1024 + cc) = pack2f(v10, v11);
            } else if (EPI == EPI_GELU) {
                v00 = gelu_f(v00 + bias[cb]);   v01 = gelu_f(v01 + bias[cb+1]);
                v10 = gelu_f(v10 + bias[cb]);   v11 = gelu_f(v11 + bias[cb+1]);
                *(uint32_t*)(Ch + (size_t)r0 * ldc + cb)     = pack2f(v00, v01);
                *(uint32_t*)(Ch + (size_t)(r0+8) * ldc + cb) = pack2f(v10, v11);
            } else {
                if (EPI == EPI_BIAS_RESID) {
                    v00 += bias[cb]; v01 += bias[cb+1];
                    v10 += bias[cb]; v11 += bias[cb+1];
                }
                float2 ra = *(const float2*)(resid + (size_t)r0 * ldc + cb);
                float2 rb = *(const float2*)(resid + (size_t)(r0+8) * ldc + cb);
                v00 += ra.x; v01 += ra.y; v10 += rb.x; v11 += rb.y;
                *(float2*)(C + (size_t)r0 * ldc + cb)     = make_float2(v00, v01);
                *(float2*)(C + (size_t)(r0+8) * ldc + cb) = make_float2(v10, v11);
            }
        }
    }
}

// ---------------------------------------------------------------------------
// tensor-core causal flash attention (fp16) — byte-exact R6/R14/R15 (proven).
// Block: 64 queries x 1 head x 1 batch, 128 threads (4 warps x 16 query rows).
// ---------------------------------------------------------------------------
#define KSTRIDE 72   /* halfs per smem row (144 B) */

__global__ __launch_bounds__(128)
void attn_tc(const __half* __restrict__ Qg,
             const __half* __restrict__ Kg, const __half* __restrict__ Vg,
             __half* __restrict__ Z)
{
    __shared__ __half Ks[2][64*KSTRIDE];
    __shared__ __half Vs[2][64*KSTRIDE];

    const int qt = (gridDim.x - 1) - blockIdx.x;   // big tiles first
    const int h  = blockIdx.y, b = blockIdx.z;
    const int tid = threadIdx.x;
    const int w = tid >> 5, lane = tid & 31;
    const int r = lane >> 2, c2 = (lane & 3) * 2;

    const uint32_t ksb = smem_to_u32(&Ks[0][0]);
    const uint32_t vsb = smem_to_u32(&Vs[0][0]);

    uint32_t qh[4][4];
    {
        size_t q0 = ((size_t)(b * SEQ + qt * 64 + w * 16 + r)) * 1024 + h * 64;
        size_t q8 = q0 + 8 * 1024;
        #pragma unroll
        for (int j = 0; j < 4; j++) {
            int kc = j * 16 + c2;
            qh[j][0] = *(const uint32_t*)(Qg + q0 + kc);
            qh[j][1] = *(const uint32_t*)(Qg + q8 + kc);
            qh[j][2] = *(const uint32_t*)(Qg + q0 + kc + 8);
            qh[j][3] = *(const uint32_t*)(Qg + q8 + kc + 8);
        }
    }

    auto load_kv = [&](int kt, int st) {
        size_t base = ((size_t)(b * SEQ + kt * 64)) * 1024 + h * 64;
        uint32_t kdst = ksb + st * (64*KSTRIDE*2);
        uint32_t vdst = vsb + st * (64*KSTRIDE*2);
        #pragma unroll
        for (int i = 0; i < 4; i++) {
            int ci = tid + 128 * i;
            int row = ci >> 3, c = ci & 7;
            cp16(kdst + row * (KSTRIDE*2) + c * 16, Kg + base + (size_t)row * 1024 + c * 8);
            cp16(vdst + row * (KSTRIDE*2) + c * 16, Vg + base + (size_t)row * 1024 + c * 8);
        }
    };

    float O[8][4];
    #pragma unroll
    for (int nt = 0; nt < 8; nt++)
        #pragma unroll
        for (int i = 0; i < 4; i++) O[nt][i] = 0.f;
    float m0 = -INFINITY, m1 = -INFINITY, l0 = 0.f, l1 = 0.f;

    const uint32_t kOff = (uint32_t)(((lane & 7) + ((lane >> 4) & 1) * 8) * (KSTRIDE*2)
                                     + ((lane >> 3) & 1) * 16);
    const uint32_t vOff = (uint32_t)(((lane & 7) + ((lane >> 3) & 1) * 8) * (KSTRIDE*2)
                                     + ((lane >> 4) & 1) * 16);

    load_kv(0, 0);
    CP_COMMIT();

    const int qrow_local = w * 16 + r;

    for (int kt = 0; kt <= qt; kt++) {
        if (kt < qt) { load_kv(kt + 1, (kt + 1) & 1); CP_COMMIT(); CP_WAIT1(); }
        else         { CP_WAIT0(); }
        __syncthreads();

        uint32_t kb_ = ksb + (kt & 1) * (64*KSTRIDE*2) + kOff;
        uint32_t vb_ = vsb + (kt & 1) * (64*KSTRIDE*2) + vOff;

        float S[8][4];
        #pragma unroll
        for (int nt = 0; nt < 8; nt++)
            #pragma unroll
            for (int i = 0; i < 4; i++) S[nt][i] = 0.f;

        #pragma unroll
        for (int j = 0; j < 4; j++) {
            uint32_t kf[8][2];
            #pragma unroll
            for (int np = 0; np < 4; np++) {
                uint32_t rr[4];
                ldm_x4(rr, kb_ + np * 16 * (KSTRIDE*2) + j * 32);
                kf[2*np][0] = rr[0]; kf[2*np][1] = rr[1];
                kf[2*np+1][0] = rr[2]; kf[2*np+1][1] = rr[3];
            }
            #pragma unroll
            for (int nt = 0; nt < 8; nt++)
                mma_fp16(S[nt], qh[j], kf[nt]);
        }

        bool diag = (kt == qt);
        #pragma unroll
        for (int nt = 0; nt < 8; nt++) {
            #pragma unroll
            for (int i = 0; i < 4; i++) {
                float s = S[nt][i] * 0.125f;
                if (diag) {
                    int col = nt * 8 + c2 + (i & 1);
                    int row = qrow_local + ((i >> 1) << 3);
                    if (col > row) s = -INFINITY;
                }
                S[nt][i] = s;
            }
        }

        float t0 = -INFINITY, t1 = -INFINITY;
        #pragma unroll
        for (int nt = 0; nt < 8; nt++) {
            t0 = fmaxf(t0, fmaxf(S[nt][0], S[nt][1]));
            t1 = fmaxf(t1, fmaxf(S[nt][2], S[nt][3]));
        }
        t0 = fmaxf(t0, __shfl_xor_sync(0xffffffffu, t0, 1));
        t0 = fmaxf(t0, __shfl_xor_sync(0xffffffffu, t0, 2));
        t1 = fmaxf(t1, __shfl_xor_sync(0xffffffffu, t1, 1));
        t1 = fmaxf(t1, __shfl_xor_sync(0xffffffffu, t1, 2));

        float mn0 = fmaxf(m0, t0), mn1 = fmaxf(m1, t1);
        float corr0 = __expf(m0 - mn0), corr1 = __expf(m1 - mn1);
        m0 = mn0; m1 = mn1;

        uint32_t P[8][2];
        float ps0 = 0.f, ps1 = 0.f;
        #pragma unroll
        for (int nt = 0; nt < 8; nt++) {
            float p00 = __expf(S[nt][0] - mn0);
            float p01 = __expf(S[nt][1] - mn0);
            float p10 = __expf(S[nt][2] - mn1);
            float p11 = __expf(S[nt][3] - mn1);
            ps0 += p00 + p01; ps1 += p10 + p11;
            P[nt][0] = pack2f(p00, p01);
            P[nt][1] = pack2f(p10, p11);
        }
        ps0 += __shfl_xor_sync(0xffffffffu, ps0, 1);
        ps0 += __shfl_xor_sync(0xffffffffu, ps0, 2);
        ps1 += __shfl_xor_sync(0xffffffffu, ps1, 1);
        ps1 += __shfl_xor_sync(0xffffffffu, ps1, 2);
        l0 = l0 * corr0 + ps0;
        l1 = l1 * corr1 + ps1;

        #pragma unroll
        for (int nt = 0; nt < 8; nt++) {
            O[nt][0] *= corr0; O[nt][1] *= corr0;
            O[nt][2] *= corr1; O[nt][3] *= corr1;
        }

        #pragma unroll
        for (int j = 0; j < 4; j++) {
            uint32_t pf[4] = { P[2*j][0], P[2*j][1], P[2*j+1][0], P[2*j+1][1] };
            uint32_t vf[8][2];
            #pragma unroll
            for (int np = 0; np < 4; np++) {
                uint32_t rr[4];
                ldm_x4t(rr, vb_ + j * 16 * (KSTRIDE*2) + np * 32);
                vf[2*np][0] = rr[0]; vf[2*np][1] = rr[1];
                vf[2*np+1][0] = rr[2]; vf[2*np+1][1] = rr[3];
            }
            #pragma unroll
            for (int nt = 0; nt < 8; nt++)
                mma_fp16(O[nt], pf, vf[nt]);
        }
        __syncthreads();
    }

    float inv0 = 1.0f / l0, inv1 = 1.0f / l1;
    size_t z0 = ((size_t)(b * SEQ + qt * 64 + qrow_local)) * 1024 + h * 64 + c2;
    size_t z8 = z0 + 8 * 1024;
    #pragma unroll
    for (int nt = 0; nt < 8; nt++) {
        *(uint32_t*)(Z + z0 + nt*8) = pack2f(O[nt][0] * inv0, O[nt][1] * inv0);
        *(uint32_t*)(Z + z8 + nt*8) = pack2f(O[nt][2] * inv1, O[nt][3] * inv1);
    }
}

// ---------------------------------------------------------------------------
// host orchestration (fork-join: transposes on side stream, proven R15)
// ---------------------------------------------------------------------------
extern "C" void kernel_launch(void* const* d_in, const int* in_sizes, int n_in,
                              void* d_out, int out_size)
{
    const float* resid = (const float*)d_in[0];
    const float* w_q   = (const float*)d_in[1];
    const float* w_k   = (const float*)d_in[2];
    const float* w_v   = (const float*)d_in[3];
    const float* w_o   = (const float*)d_in[4];
    const float* ln1_w = (const float*)d_in[5];
    const float* ln1_b = (const float*)d_in[6];
    const float* ln2_w = (const float*)d_in[7];
    const float* ln2_b = (const float*)d_in[8];
    const float* w_in  = (const float*)d_in[9];
    const float* b_in  = (const float*)d_in[10];
    const float* w_out = (const float*)d_in[11];
    const float* b_out = (const float*)d_in[12];
    float* out = (float*)d_out;

    float *r2;
    __half *ln1, *ln2, *qg, *kg, *vg, *z, *hb;
    __half *Bqkv, *Bo, *Bin, *Bout;
    cudaGetSymbolAddress((void**)&r2,   g_r2);
    cudaGetSymbolAddress((void**)&ln1,  g_ln1);
    cudaGetSymbolAddress((void**)&ln2,  g_ln2);
    cudaGetSymbolAddress((void**)&qg,   g_Qg);
    cudaGetSymbolAddress((void**)&kg,   g_Kg);
    cudaGetSymbolAddress((void**)&vg,   g_Vg);
    cudaGetSymbolAddress((void**)&z,    g_z);
    cudaGetSymbolAddress((void**)&hb,   g_h);
    cudaGetSymbolAddress((void**)&Bqkv, g_Bqkv);
    cudaGetSymbolAddress((void**)&Bo,   g_Bo);
    cudaGetSymbolAddress((void**)&Bin,  g_Bin);
    cudaGetSymbolAddress((void**)&Bout, g_Bout);

    cudaFuncSetAttribute(gemm_mma<EPI_QKV>,        cudaFuncAttributeMaxDynamicSharedMemorySize, GEMM_SMEM);
    cudaFuncSetAttribute(gemm_mma<EPI_RESID>,      cudaFuncAttributeMaxDynamicSharedMemorySize, GEMM_SMEM);
    cudaFuncSetAttribute(gemm_mma<EPI_GELU>,       cudaFuncAttributeMaxDynamicSharedMemorySize, GEMM_SMEM);
    cudaFuncSetAttribute(gemm_mma<EPI_BIAS_RESID>, cudaFuncAttributeMaxDynamicSharedMemorySize, GEMM_SMEM);

    // ---- fork: side stream does all weight transposes ----
    cudaEventRecord(g_e0, 0);
    cudaStreamWaitEvent(g_s1, g_e0, 0);

    transpose_h<<<dim3(2, 32, 16), 256, 0, g_s1>>>(w_q, Bqkv,             1024, 64, 65536, 65536);
    transpose_h<<<dim3(2, 32, 16), 256, 0, g_s1>>>(w_k, Bqkv + 1024*1024, 1024, 64, 65536, 65536);
    transpose_h<<<dim3(2, 32, 16), 256, 0, g_s1>>>(w_v, Bqkv + 2048*1024, 1024, 64, 65536, 65536);
    cudaEventRecord(g_e1, g_s1);          // Bqkv ready

    transpose_h<<<dim3(32, 32, 1),  256, 0, g_s1>>>(w_o,   Bo,   1024, 1024, 0, 0);
    transpose_h<<<dim3(128, 32, 1), 256, 0, g_s1>>>(w_in,  Bin,  1024, 4096, 0, 0);
    transpose_h<<<dim3(32, 128, 1), 256, 0, g_s1>>>(w_out, Bout, 4096, 1024, 0, 0);
    cudaEventRecord(g_e2, g_s1);          // Bo/Bin/Bout ready

    // ---- main stream: ln1 overlaps Bqkv transposes ----
    ln_h_kernel<<<MROWS, 256>>>(resid, ln1_w, ln1_b, ln1);

    cudaStreamWaitEvent(0, g_e1, 0);      // join: Bqkv needed now
    gemm_mma<EPI_QKV><<<dim3(24, 32), 256, GEMM_SMEM>>>(
        ln1, Bqkv, nullptr, qg, kg, vg, 1024, 3072, nullptr, nullptr);

    attn_tc<<<dim3(SEQ / 64, N_HEADS, BATCH), 128>>>(qg, kg, vg, z);

    cudaStreamWaitEvent(0, g_e2, 0);      // join: Bo/Bin/Bout needed from here
    gemm_mma<EPI_RESID><<<dim3(8, 32), 256, GEMM_SMEM>>>(
        z, Bo, r2, nullptr, nullptr, nullptr, 1024, 1024, nullptr, resid);

    ln_h_kernel<<<MROWS, 256>>>(r2, ln2_w, ln2_b, ln2);

    gemm_mma<EPI_GELU><<<dim3(32, 32), 256, GEMM_SMEM>>>(
        ln2, Bin, nullptr, hb, nullptr, nullptr, 1024, 4096, b_in, nullptr);

    gemm_mma<EPI_BIAS_RESID><<<dim3(8, 32), 256, GEMM_SMEM>>>(
        hb, Bout, out, nullptr, nullptr, nullptr, 4096, 1024, b_out, r2);
}